// round 2
// baseline (speedup 1.0000x reference)
#include <cuda_runtime.h>
#include <cstdint>

// Problem constants
#define B_   2048
#define D_   1024
#define U_   1024
#define L_   3
#define NB   8                       // NUM_BASIS
#define FEAT (D_ + D_ * NB)          // 9216: [silu(x) | bases(d*8+k)]

// Scratch (static device globals: allocation-guard safe)
__device__ float g_feat[(size_t)B_ * FEAT];     // [B, 9216]
__device__ float g_z   [(size_t)B_ * 4 * U_];   // [B, 4096] LSTM pre-activations
__device__ float g_comb[(size_t)B_ * 4 * U_];   // [B, 4096] = [h | kan0 | kan1 | kan2]

// ---------------------------------------------------------------------------
// Featurize: silu(x) and order-3 B-spline bases (Cox-de Boor, 12 uniform knots)
// ---------------------------------------------------------------------------
__global__ void featurize_kernel(const float* __restrict__ x) {
    int idx = blockIdx.x * blockDim.x + threadIdx.x;
    if (idx >= B_ * D_) return;
    int b = idx / D_;
    int d = idx - b * D_;
    float xv = x[idx];

    // silu
    float s = xv / (1.0f + expf(-xv));
    g_feat[(size_t)b * FEAT + d] = s;

    // knots t_i = -1 + 0.4*(i-3), i = 0..11 (fp64 -> fp32, matching reference)
    float t[12];
#pragma unroll
    for (int i = 0; i < 12; i++) t[i] = (float)(-1.0 + 0.4 * (double)(i - 3));

    float bb[11];
#pragma unroll
    for (int i = 0; i < 11; i++) bb[i] = (xv >= t[i] && xv < t[i + 1]) ? 1.0f : 0.0f;

#pragma unroll
    for (int p = 1; p <= 3; p++) {
#pragma unroll
        for (int i = 0; i < 11; i++) {
            if (i < 11 - p) {
                float left  = (xv - t[i])         / (t[i + p]     - t[i])     * bb[i];
                float right = (t[i + p + 1] - xv) / (t[i + p + 1] - t[i + 1]) * bb[i + 1];
                bb[i] = left + right;
            }
        }
    }

    float* dst = &g_feat[(size_t)b * FEAT + D_ + d * NB];
#pragma unroll
    for (int k = 0; k < NB; k++) dst[k] = bb[k];
}

// ---------------------------------------------------------------------------
// LSTM gates: z + bias -> c, h. Writes h,c to d_out; h also into comb[:,0:U].
// ---------------------------------------------------------------------------
__global__ void gates_kernel(const float* __restrict__ c_prev,
                             const float* __restrict__ bias,
                             float* __restrict__ h_out,
                             float* __restrict__ c_out) {
    int idx = blockIdx.x * blockDim.x + threadIdx.x;
    if (idx >= B_ * U_) return;
    int b = idx / U_;
    int u = idx - b * U_;
    const float* zr = &g_z[(size_t)b * 4 * U_];
    float zi = zr[u]          + bias[u];
    float zf = zr[U_ + u]     + bias[U_ + u];
    float zg = zr[2 * U_ + u] + bias[2 * U_ + u];
    float zo = zr[3 * U_ + u] + bias[3 * U_ + u];
    float si = 1.0f / (1.0f + expf(-zi));
    float sf = 1.0f / (1.0f + expf(-zf));
    float so = 1.0f / (1.0f + expf(-zo));
    float c  = sf * c_prev[idx] + si * tanhf(zg);
    float h  = so * tanhf(c);
    c_out[idx] = c;
    h_out[idx] = h;
    g_comb[(size_t)b * 4 * U_ + u] = h;
}

// ---------------------------------------------------------------------------
// Dual-segment SGEMM: C[M,N] = A1[M,K1]@B1[K1,N] + A2[M,K2]@B2[K2,N] (+bias)
// Row-major, BM=BN=128, BK=8, 256 threads, 8x8 microtile, double-buffered smem.
// Requires M%128==0, N%128==0, K1%8==0, K2%8==0. (All hold here.)
// ---------------------------------------------------------------------------
template <int BIAS>
__global__ void __launch_bounds__(256, 2)
gemm2_kernel(const float* __restrict__ A1, int lda1,
             const float* __restrict__ B1, int ldb1, int K1,
             const float* __restrict__ A2, int lda2,
             const float* __restrict__ B2, int ldb2, int K2,
             float* __restrict__ C, int ldc,
             const float* __restrict__ bias) {
    __shared__ float As[2][8][136];   // padded: conflict-light + float4-aligned
    __shared__ float Bs[2][8][128];

    const int tid = threadIdx.x;
    const int bm = blockIdx.y * 128;
    const int bn = blockIdx.x * 128;

    // A loader: 128 rows x 8 cols, float4 per thread
    const int arow = tid >> 1;          // 0..127
    const int acol = (tid & 1) * 4;     // 0 or 4
    // B loader: 8 rows x 128 cols, float4 per thread
    const int brow = tid >> 5;          // 0..7
    const int bcol = (tid & 31) * 4;    // 0..124

    const int tx = tid & 15;            // col group (8 cols)
    const int ty = tid >> 4;            // row group (8 rows)

    float acc[8][8];
#pragma unroll
    for (int i = 0; i < 8; i++)
#pragma unroll
        for (int j = 0; j < 8; j++) acc[i][j] = 0.0f;

    const size_t arowOff1 = (size_t)(bm + arow) * lda1;
    const size_t arowOff2 = (size_t)(bm + arow) * lda2;
    const int Ktot = K1 + K2;

    float4 av, bv;
    // prologue: fetch k0 = 0 (K1 >= 8 always)
    av = *(const float4*)(A1 + arowOff1 + acol);
    bv = *(const float4*)(B1 + (size_t)brow * ldb1 + bn + bcol);

    int buf = 0;
    As[buf][acol + 0][arow] = av.x;
    As[buf][acol + 1][arow] = av.y;
    As[buf][acol + 2][arow] = av.z;
    As[buf][acol + 3][arow] = av.w;
    *(float4*)&Bs[buf][brow][bcol] = bv;
    __syncthreads();

    for (int k0 = 8; k0 <= Ktot; k0 += 8) {
        if (k0 < Ktot) {
            const float* Ap;
            const float* Bp;
            if (k0 < K1) {
                Ap = A1 + arowOff1 + k0 + acol;
                Bp = B1 + (size_t)(k0 + brow) * ldb1 + bn + bcol;
            } else {
                int k2 = k0 - K1;
                Ap = A2 + arowOff2 + k2 + acol;
                Bp = B2 + (size_t)(k2 + brow) * ldb2 + bn + bcol;
            }
            av = *(const float4*)Ap;
            bv = *(const float4*)Bp;
        }

        // compute on current buffer
#pragma unroll
        for (int kk = 0; kk < 8; kk++) {
            float a[8], b[8];
            *(float4*)&a[0] = *(const float4*)&As[buf][kk][ty * 8];
            *(float4*)&a[4] = *(const float4*)&As[buf][kk][ty * 8 + 4];
            *(float4*)&b[0] = *(const float4*)&Bs[buf][kk][tx * 8];
            *(float4*)&b[4] = *(const float4*)&Bs[buf][kk][tx * 8 + 4];
#pragma unroll
            for (int i = 0; i < 8; i++)
#pragma unroll
                for (int j = 0; j < 8; j++) acc[i][j] += a[i] * b[j];
        }

        if (k0 < Ktot) {
            buf ^= 1;
            As[buf][acol + 0][arow] = av.x;
            As[buf][acol + 1][arow] = av.y;
            As[buf][acol + 2][arow] = av.z;
            As[buf][acol + 3][arow] = av.w;
            *(float4*)&Bs[buf][brow][bcol] = bv;
            __syncthreads();
        }
    }

    // Epilogue
#pragma unroll
    for (int i = 0; i < 8; i++) {
        int row = bm + ty * 8 + i;
        float* cp = C + (size_t)row * ldc + bn + tx * 8;
#pragma unroll
        for (int j = 0; j < 8; j += 4) {
            float4 v;
            v.x = acc[i][j];     v.y = acc[i][j + 1];
            v.z = acc[i][j + 2]; v.w = acc[i][j + 3];
            if (BIAS) {
                int col = bn + tx * 8 + j;
                v.x += bias[col];     v.y += bias[col + 1];
                v.z += bias[col + 2]; v.w += bias[col + 3];
            }
            *(float4*)(cp + j) = v;
        }
    }
}

// ---------------------------------------------------------------------------
// Launch
// ---------------------------------------------------------------------------
extern "C" void kernel_launch(void* const* d_in, const int* in_sizes, int n_in,
                              void* d_out, int out_size) {
    const float* x        = (const float*)d_in[0];
    const float* h_prev   = (const float*)d_in[1];
    const float* c_prev   = (const float*)d_in[2];
    const float* Wk       = (const float*)d_in[3];   // [D, 4U]
    const float* Wr       = (const float*)d_in[4];   // [U, 4U]
    const float* lbias    = (const float*)d_in[5];   // [4U]
    const float* base_w   = (const float*)d_in[6];   // [L, D, U]
    const float* spline_w = (const float*)d_in[7];   // [L, D*NB, U]
    const float* comb_w   = (const float*)d_in[8];   // [4U, U]
    const float* comb_b   = (const float*)d_in[9];   // [U]

    float* out   = (float*)d_out;            // [B, U]
    float* h_out = out + (size_t)B_ * U_;    // [B, U]
    float* c_out = out + (size_t)2 * B_ * U_;

    float *feat, *z, *comb;
    cudaGetSymbolAddress((void**)&feat, g_feat);
    cudaGetSymbolAddress((void**)&z,    g_z);
    cudaGetSymbolAddress((void**)&comb, g_comb);

    const int T = 256;

    // 1. features (silu + bases)
    featurize_kernel<<<(B_ * D_ + T - 1) / T, T>>>(x);

    // 2. LSTM pre-activations: z = x@Wk + h_prev@Wr  (single dual-segment GEMM)
    gemm2_kernel<0><<<dim3(4 * U_ / 128, B_ / 128), T>>>(
        x, D_, Wk, 4 * U_, D_,
        h_prev, U_, Wr, 4 * U_, U_,
        z, 4 * U_, nullptr);

    // 3. gates -> h, c (also fills comb[:, 0:U])
    gates_kernel<<<(B_ * U_ + T - 1) / T, T>>>(c_prev, lbias, h_out, c_out);

    // 4. KAN layers: comb[:, (1+l)U:(2+l)U] = silu(x)@base_w[l] + bases@spline_w[l]
    for (int l = 0; l < L_; l++) {
        float* cl = comb + (size_t)(1 + l) * U_;
        gemm2_kernel<0><<<dim3(U_ / 128, B_ / 128), T>>>(
            feat,      FEAT, base_w   + (size_t)l * D_ * U_,      U_, D_,
            feat + D_, FEAT, spline_w + (size_t)l * D_ * NB * U_, U_, D_ * NB,
            cl, 4 * U_, nullptr);
    }

    // 5. combine: out = comb @ comb_w + comb_b  (second segment empty)
    gemm2_kernel<1><<<dim3(U_ / 128, B_ / 128), T>>>(
        comb, 4 * U_, comb_w, U_, 4 * U_,
        comb, 4 * U_, comb_w, U_, 0,
        out, U_, comb_b);
}

// round 3
// speedup vs baseline: 1.5702x; 1.5702x over previous
#include <cuda_runtime.h>
#include <cstdint>

// Problem constants
#define B_   2048
#define D_   1024
#define U_   1024
#define L_   3
#define NB   8                       // NUM_BASIS
#define FEAT (D_ + D_ * NB)          // 9216: [silu(x) | bases(d*8+k)]

// Scratch (static device globals: allocation-guard safe)
__device__ float g_feat[(size_t)B_ * FEAT];     // [B, 9216]
__device__ float g_z   [(size_t)B_ * 4 * U_];   // [B, 4096] LSTM pre-activations
__device__ float g_comb[(size_t)B_ * 4 * U_];   // [B, 4096] = [h | kan0 | kan1 | kan2]

// ---------------------------------------------------------------------------
// Featurize: silu(x) and order-3 B-spline bases (Cox-de Boor, 12 uniform knots)
// ---------------------------------------------------------------------------
__global__ void featurize_kernel(const float* __restrict__ x) {
    int idx = blockIdx.x * blockDim.x + threadIdx.x;
    if (idx >= B_ * D_) return;
    int b = idx / D_;
    int d = idx - b * D_;
    float xv = x[idx];

    float s = xv / (1.0f + expf(-xv));
    g_feat[(size_t)b * FEAT + d] = s;

    float t[12];
#pragma unroll
    for (int i = 0; i < 12; i++) t[i] = (float)(-1.0 + 0.4 * (double)(i - 3));

    float bb[11];
#pragma unroll
    for (int i = 0; i < 11; i++) bb[i] = (xv >= t[i] && xv < t[i + 1]) ? 1.0f : 0.0f;

#pragma unroll
    for (int p = 1; p <= 3; p++) {
#pragma unroll
        for (int i = 0; i < 11; i++) {
            if (i < 11 - p) {
                float left  = (xv - t[i])         / (t[i + p]     - t[i])     * bb[i];
                float right = (t[i + p + 1] - xv) / (t[i + p + 1] - t[i + 1]) * bb[i + 1];
                bb[i] = left + right;
            }
        }
    }

    float* dst = &g_feat[(size_t)b * FEAT + D_ + d * NB];
#pragma unroll
    for (int k = 0; k < NB; k++) dst[k] = bb[k];
}

// ---------------------------------------------------------------------------
// LSTM gates
// ---------------------------------------------------------------------------
__global__ void gates_kernel(const float* __restrict__ c_prev,
                             const float* __restrict__ bias,
                             float* __restrict__ h_out,
                             float* __restrict__ c_out) {
    int idx = blockIdx.x * blockDim.x + threadIdx.x;
    if (idx >= B_ * U_) return;
    int b = idx / U_;
    int u = idx - b * U_;
    const float* zr = &g_z[(size_t)b * 4 * U_];
    float zi = zr[u]          + bias[u];
    float zf = zr[U_ + u]     + bias[U_ + u];
    float zg = zr[2 * U_ + u] + bias[2 * U_ + u];
    float zo = zr[3 * U_ + u] + bias[3 * U_ + u];
    float si = 1.0f / (1.0f + expf(-zi));
    float sf = 1.0f / (1.0f + expf(-zf));
    float so = 1.0f / (1.0f + expf(-zo));
    float c  = sf * c_prev[idx] + si * tanhf(zg);
    float h  = so * tanhf(c);
    c_out[idx] = c;
    h_out[idx] = h;
    g_comb[(size_t)b * 4 * U_ + u] = h;
}

// ---------------------------------------------------------------------------
// TF32 tensor-core dual-segment GEMM.
// C[M,N] = A1[M,K1]@B1 + A2[M,K2]@B2 (+bias). Row-major everywhere.
// BM=BN=128, BK=8, 256 threads (8 warps = 2x4 of 64x32 warp tiles),
// mma.sync.m16n8k8.tf32, double-buffered smem.
// Requires M%128==0, N%128==0, K1%8==0, K2%8==0.
// ---------------------------------------------------------------------------
__device__ __forceinline__ float to_tf32(float x) {
    float r;
    asm("cvt.rna.tf32.f32 %0, %1;" : "=f"(r) : "f"(x));
    return r;
}

__device__ __forceinline__ void mma_tf32(float c[4],
                                         uint32_t a0, uint32_t a1, uint32_t a2, uint32_t a3,
                                         uint32_t b0, uint32_t b1) {
    asm volatile(
        "mma.sync.aligned.m16n8k8.row.col.f32.tf32.tf32.f32 "
        "{%0,%1,%2,%3}, {%4,%5,%6,%7}, {%8,%9}, {%0,%1,%2,%3};"
        : "+f"(c[0]), "+f"(c[1]), "+f"(c[2]), "+f"(c[3])
        : "r"(a0), "r"(a1), "r"(a2), "r"(a3), "r"(b0), "r"(b1));
}

#define ASTR 132   // float2 row stride for As (skewed: conflict-optimal)
#define BSTR 136   // float row stride for Bs (conflict-free fragment loads)

template <int BIAS>
__global__ void __launch_bounds__(256, 2)
gemm2_tc(const float* __restrict__ A1, int lda1,
         const float* __restrict__ B1, int ldb1, int K1,
         const float* __restrict__ A2, int lda2,
         const float* __restrict__ B2, int ldb2, int K2,
         float* __restrict__ C, int ldc,
         const float* __restrict__ bias) {
    // As2[buf][q][r] = (A[r, q], A[r, q+4]) as float2, q = k%4 pairing
    __shared__ float2 As2[2][4][ASTR];
    __shared__ float  Bs [2][8][BSTR];

    const int tid  = threadIdx.x;
    const int lane = tid & 31;
    const int wid  = tid >> 5;
    const int g    = lane >> 2;      // group id 0..7
    const int t    = lane & 3;       // thread in group 0..3
    const int wm   = (wid >> 2) * 64;  // warp M offset (0/64)
    const int wn   = (wid & 3) * 32;   // warp N offset (0/32/64/96)

    const int bm = blockIdx.y * 128;
    const int bn = blockIdx.x * 128;

    // A loader: r = tid>>1 (0..127), half = tid&1 -> cols half*4 .. half*4+3
    const int ar   = tid >> 1;
    const int ahalf = tid & 1;
    // B loader: row = tid>>5 (0..7), c4 = tid&31 -> cols c4*4..c4*4+3
    const int br  = tid >> 5;
    const int bc4 = (tid & 31) * 4;

    const size_t aoff1 = (size_t)(bm + ar) * lda1 + ahalf * 4;
    const size_t aoff2 = (size_t)(bm + ar) * lda2 + ahalf * 4;

    float acc[4][4][4];
#pragma unroll
    for (int i = 0; i < 4; i++)
#pragma unroll
        for (int j = 0; j < 4; j++)
#pragma unroll
            for (int v = 0; v < 4; v++) acc[i][j][v] = 0.0f;

    const int Ktot = K1 + K2;

    // prologue: k0 = 0 (always segment 1)
    float4 av = *(const float4*)(A1 + aoff1);
    float4 bv = *(const float4*)(B1 + (size_t)br * ldb1 + bn + bc4);

    int buf = 0;
    {
        float va[4] = {to_tf32(av.x), to_tf32(av.y), to_tf32(av.z), to_tf32(av.w)};
#pragma unroll
        for (int i = 0; i < 4; i++)
            ((float*)&As2[buf][i][ar])[ahalf] = va[i];
        float4 vb;
        vb.x = to_tf32(bv.x); vb.y = to_tf32(bv.y);
        vb.z = to_tf32(bv.z); vb.w = to_tf32(bv.w);
        *(float4*)&Bs[buf][br][bc4] = vb;
    }
    __syncthreads();

    for (int k0 = 8; k0 <= Ktot; k0 += 8) {
        if (k0 < Ktot) {
            if (k0 < K1) {
                av = *(const float4*)(A1 + aoff1 + k0);
                bv = *(const float4*)(B1 + (size_t)(k0 + br) * ldb1 + bn + bc4);
            } else {
                int k2 = k0 - K1;
                av = *(const float4*)(A2 + aoff2 + k2);
                bv = *(const float4*)(B2 + (size_t)(k2 + br) * ldb2 + bn + bc4);
            }
        }

        // ---- compute on current buffer ----
        uint32_t a[4][4];   // [mi][frag]
        uint32_t b[4][2];   // [ni][frag]
#pragma unroll
        for (int mi = 0; mi < 4; mi++) {
            float2 p0 = As2[buf][t][wm + mi * 16 + g];
            float2 p1 = As2[buf][t][wm + mi * 16 + g + 8];
            a[mi][0] = __float_as_uint(p0.x);   // (g,     t)
            a[mi][1] = __float_as_uint(p1.x);   // (g+8,   t)
            a[mi][2] = __float_as_uint(p0.y);   // (g,     t+4)
            a[mi][3] = __float_as_uint(p1.y);   // (g+8,   t+4)
        }
#pragma unroll
        for (int ni = 0; ni < 4; ni++) {
            b[ni][0] = __float_as_uint(Bs[buf][t][wn + ni * 8 + g]);      // (t,   n)
            b[ni][1] = __float_as_uint(Bs[buf][t + 4][wn + ni * 8 + g]);  // (t+4, n)
        }
#pragma unroll
        for (int mi = 0; mi < 4; mi++)
#pragma unroll
            for (int ni = 0; ni < 4; ni++)
                mma_tf32(acc[mi][ni], a[mi][0], a[mi][1], a[mi][2], a[mi][3],
                         b[ni][0], b[ni][1]);

        if (k0 < Ktot) {
            buf ^= 1;
            float va[4] = {to_tf32(av.x), to_tf32(av.y), to_tf32(av.z), to_tf32(av.w)};
#pragma unroll
            for (int i = 0; i < 4; i++)
                ((float*)&As2[buf][i][ar])[ahalf] = va[i];
            float4 vb;
            vb.x = to_tf32(bv.x); vb.y = to_tf32(bv.y);
            vb.z = to_tf32(bv.z); vb.w = to_tf32(bv.w);
            *(float4*)&Bs[buf][br][bc4] = vb;
            __syncthreads();
        }
    }

    // ---- epilogue ----
#pragma unroll
    for (int mi = 0; mi < 4; mi++) {
        int row0 = bm + wm + mi * 16 + g;
#pragma unroll
        for (int ni = 0; ni < 4; ni++) {
            int col = bn + wn + ni * 8 + 2 * t;
            float2 v0, v1;
            v0.x = acc[mi][ni][0]; v0.y = acc[mi][ni][1];
            v1.x = acc[mi][ni][2]; v1.y = acc[mi][ni][3];
            if (BIAS) {
                v0.x += bias[col]; v0.y += bias[col + 1];
                v1.x += bias[col]; v1.y += bias[col + 1];
            }
            *(float2*)(C + (size_t)row0 * ldc + col)       = v0;
            *(float2*)(C + (size_t)(row0 + 8) * ldc + col) = v1;
        }
    }
}

// ---------------------------------------------------------------------------
// Launch
// ---------------------------------------------------------------------------
extern "C" void kernel_launch(void* const* d_in, const int* in_sizes, int n_in,
                              void* d_out, int out_size) {
    const float* x        = (const float*)d_in[0];
    const float* h_prev   = (const float*)d_in[1];
    const float* c_prev   = (const float*)d_in[2];
    const float* Wk       = (const float*)d_in[3];   // [D, 4U]
    const float* Wr       = (const float*)d_in[4];   // [U, 4U]
    const float* lbias    = (const float*)d_in[5];   // [4U]
    const float* base_w   = (const float*)d_in[6];   // [L, D, U]
    const float* spline_w = (const float*)d_in[7];   // [L, D*NB, U]
    const float* comb_w   = (const float*)d_in[8];   // [4U, U]
    const float* comb_b   = (const float*)d_in[9];   // [U]

    float* out   = (float*)d_out;            // [B, U]
    float* h_out = out + (size_t)B_ * U_;    // [B, U]
    float* c_out = out + (size_t)2 * B_ * U_;

    float *feat, *z, *comb;
    cudaGetSymbolAddress((void**)&feat, g_feat);
    cudaGetSymbolAddress((void**)&z,    g_z);
    cudaGetSymbolAddress((void**)&comb, g_comb);

    const int T = 256;

    // 1. features (silu + bases)
    featurize_kernel<<<(B_ * D_ + T - 1) / T, T>>>(x);

    // 2. LSTM pre-activations: z = x@Wk + h_prev@Wr
    gemm2_tc<0><<<dim3(4 * U_ / 128, B_ / 128), T>>>(
        x, D_, Wk, 4 * U_, D_,
        h_prev, U_, Wr, 4 * U_, U_,
        z, 4 * U_, nullptr);

    // 3. gates -> h, c (also fills comb[:, 0:U])
    gates_kernel<<<(B_ * U_ + T - 1) / T, T>>>(c_prev, lbias, h_out, c_out);

    // 4. KAN layers: comb[:, (1+l)U:(2+l)U] = silu(x)@base_w[l] + bases@spline_w[l]
    for (int l = 0; l < L_; l++) {
        float* cl = comb + (size_t)(1 + l) * U_;
        gemm2_tc<0><<<dim3(U_ / 128, B_ / 128), T>>>(
            feat,      FEAT, base_w   + (size_t)l * D_ * U_,      U_, D_,
            feat + D_, FEAT, spline_w + (size_t)l * D_ * NB * U_, U_, D_ * NB,
            cl, 4 * U_, nullptr);
    }

    // 5. combine: out = comb @ comb_w + comb_b  (second segment empty)
    gemm2_tc<1><<<dim3(U_ / 128, B_ / 128), T>>>(
        comb, 4 * U_, comb_w, U_, 4 * U_,
        comb, 4 * U_, comb_w, U_, 0,
        out, U_, comb_b);
}